// round 15
// baseline (speedup 1.0000x reference)
#include <cuda_runtime.h>

#define TPB 128
#define APT 4                 // anchors per thread (k_phase1)
#define CHUNK (TPB * APT)     // anchors per block = 512
#define NW   (TPB / 32)       // warps per block
#define MAXN 128              // max gt boxes per image supported
#define MAXB 16               // max batch
#define K3T 256               // k_phase3 threads
#define K3A 512               // anchors per k_phase3 block

// Scratch (device globals; no allocation allowed)
__device__ unsigned long long g_partial[1 << 19];  // per-(b,n) per-chunk best keys
__device__ unsigned long long g_abest[1 << 20];    // per-(b,a) packed (iou, box idx)
__device__ float2             g_nbest[MAXB * MAXN];// per-(b,n): (miou, argmax anchor)

// K1: for each (batch, 512-anchor chunk): compute all IoUs vs N boxes once.
//  - per-anchor best (axis=1 argmax, strict > = first occurrence) -> g_abest
//  - per-box block-best (axis=0 argmax candidate) -> g_partial
//  Trims vs the clamped-scalar version:
//   * h left unclamped: iou <= 0 whenever the pair doesn't overlap, which loses
//     every strict-> comparison against the 0-initialized bests — identical
//     decisions to the reference's exact-0; overlapping pairs are bit-identical.
//   * merged per-box max clamped ONCE per thread before the warp REDUX.
//   * single REDUX.MAX; max-holding lanes plain-store their key to swb (race on
//     bit-equal positive IoU is measure-zero; swb pre-initialized to the
//     (0, anchor 0) key so never-overlapping boxes match the reference argmax).
__global__ void __launch_bounds__(TPB)
k_phase1(const float4* __restrict__ anchors, const float4* __restrict__ bboxes,
         int A, int N, int numChunks)
{
    __shared__ float4 sbox[MAXN];
    __shared__ float  sarea[MAXN];
    __shared__ unsigned long long swb[MAXN * NW];

    const int b = blockIdx.y, chunk = blockIdx.x, tid = threadIdx.x;
    const int wid = tid >> 5;

    for (int n = tid; n < N; n += TPB) {
        float4 bb = bboxes[b * N + n];
        sbox[n] = bb;
        sarea[n] = (bb.z - bb.x) * (bb.w - bb.y);
    }
    // init per-(box,warp) keys to (iou=0, anchor 0): matches reference argmax
    // of an all-zero column.
    for (int i = tid; i < N * NW; i += TPB) swb[i] = 0x00000000FFFFFFFFull;
    __syncthreads();

    // Load APT anchors (stride TPB so within-warp anchor order == lane order)
    float ax1[APT], ay1[APT], ax2[APT], ay2[APT], areaA[APT];
    unsigned aidx[APT];
    bool avalid[APT];
    #pragma unroll
    for (int k = 0; k < APT; k++) {
        int a = chunk * CHUNK + k * TPB + tid;
        aidx[k] = (unsigned)a;
        avalid[k] = (a < A);
        if (avalid[k]) {
            float4 c = anchors[a];
            ax1[k] = c.x - c.z * 0.5f;  ay1[k] = c.y - c.w * 0.5f;
            ax2[k] = c.x + c.z * 0.5f;  ay2[k] = c.y + c.w * 0.5f;
            areaA[k] = (ax2[k] - ax1[k]) * (ay2[k] - ay1[k]);  // reference order
        } else {
            // dummy: zero extent -> IoU <= 0 vs any valid box; index larger than
            // every real anchor so it never wins.
            ax1[k] = 0.f; ay1[k] = 0.f; ax2[k] = 0.f; ay2[k] = 0.f;
            areaA[k] = 0.f;
        }
    }

    float bestI[APT];
    int   bestN[APT];
    #pragma unroll
    for (int k = 0; k < APT; k++) { bestI[k] = 0.0f; bestN[k] = 0; }

    #pragma unroll 2
    for (int n = 0; n < N; n++) {
        float4 bb = sbox[n];
        float sa = sarea[n];

        float iou[APT];
        #pragma unroll
        for (int k = 0; k < APT; k++) {
            float ltx = fmaxf(ax1[k], bb.x), lty = fmaxf(ay1[k], bb.y);
            float rbx = fminf(ax2[k], bb.z), rby = fminf(ay2[k], bb.w);
            float w = fmaxf(rbx - ltx, 0.f);
            float h = rby - lty;                       // unclamped
            float inter = w * h;                       // <=0 if no overlap
            float asum = areaA[k] + sa;
            iou[k] = __fdividef(inter, asum - inter);
        }

        // per-anchor running argmax (strict >, 0-init: non-overlap never wins)
        #pragma unroll
        for (int k = 0; k < APT; k++)
            if (iou[k] > bestI[k]) { bestI[k] = iou[k]; bestN[k] = n; }

        // merge the APT anchors (strict > keeps earlier = lower anchor index)
        float    mi = iou[0];
        unsigned wa = aidx[0];
        #pragma unroll
        for (int k = 1; k < APT; k++)
            if (iou[k] > mi) { mi = iou[k]; wa = aidx[k]; }

        // clamp once, then warp max (uint-monotone for clamped >=0 floats).
        float mif = fmaxf(mi, 0.f);
        unsigned u = __float_as_uint(mif);
        unsigned m = __reduce_max_sync(0xffffffffu, u);
        if (u == m && m != 0u)
            swb[n * NW + wid] =
                ((unsigned long long)m << 32) | (0xFFFFFFFFu - wa);
    }

    #pragma unroll
    for (int k = 0; k < APT; k++)
        if (avalid[k])
            g_abest[(size_t)b * A + aidx[k]] =
                ((unsigned long long)__float_as_uint(bestI[k]) << 32) |
                (unsigned)bestN[k];

    __syncthreads();
    for (int n = tid; n < N; n += TPB) {
        unsigned long long best = swb[n * NW];
        #pragma unroll
        for (int w8 = 1; w8 < NW; w8++)
            if (swb[n * NW + w8] > best) best = swb[n * NW + w8];
        g_partial[((size_t)(b * N + n)) * numChunks + chunk] = best;
    }
}

// K2: reduce chunk partials per (b,n) -> (max_iou_of_bbox, anchor argmax).
__global__ void __launch_bounds__(64)
k_phase2(int A, int N, int numChunks)
{
    const int bn = blockIdx.x, tid = threadIdx.x;
    const unsigned long long* p = g_partial + (size_t)bn * numChunks;

    unsigned long long key = 0;
    for (int c = tid; c < numChunks; c += 64) {
        unsigned long long v = p[c];
        if (v > key) key = v;
    }
    __shared__ unsigned long long sred[2];
    #pragma unroll
    for (int off = 16; off; off >>= 1) {
        unsigned long long o = __shfl_down_sync(0xffffffffu, key, off);
        if (o > key) key = o;
    }
    if ((tid & 31) == 0) sred[tid >> 5] = key;
    __syncthreads();
    if (tid == 0) {
        if (sred[1] > key) key = sred[1];
        float miou = __uint_as_float((unsigned)(key >> 32));
        int   idx  = (int)(0xFFFFFFFFu - (unsigned)key);
        g_nbest[bn] = make_float2(miou, __int_as_float(idx));
    }
}

// K3: epilogue per 512-anchor block. Winner (segment_max over targets) is
// rebuilt LOCALLY in smem from the 100 per-box argmax anchors.
__global__ void __launch_bounds__(K3T)
k_phase3(const float4* __restrict__ anchors, const float4* __restrict__ bboxes,
         const int* __restrict__ labels,
         const float* __restrict__ enc_mean, const float* __restrict__ enc_std,
         const float* __restrict__ thr_ptr,
         float* __restrict__ out_conf, float4* __restrict__ out_delta,
         int A, int N, int C)
{
    __shared__ float4 sbox[MAXN];
    __shared__ int    slab[MAXN];
    __shared__ float  smiou[MAXN];
    __shared__ int    saw[MAXN];
    __shared__ int    swin[K3A];

    const int b = blockIdx.y, tid = threadIdx.x;
    const int abase = blockIdx.x * K3A;

    for (int n = tid; n < N; n += K3T) {
        sbox[n]  = bboxes[b * N + n];
        slab[n]  = labels[b * N + n];
        float2 nb = g_nbest[b * N + n];
        smiou[n] = nb.x;
        saw[n]   = __float_as_int(nb.y);
    }
    #pragma unroll
    for (int h = 0; h < K3A / K3T; h++) swin[h * K3T + tid] = -1;
    __syncthreads();

    // segment_max scatter restricted to this block's anchor range
    for (int n = tid; n < N; n += K3T) {
        int aw = saw[n] - abase;
        if ((unsigned)aw < (unsigned)K3A) atomicMax(&swin[aw], n);
    }
    __syncthreads();

    const float thr = __ldg(thr_ptr);
    const float em0 = __ldg(&enc_mean[0]), em1 = __ldg(&enc_mean[1]);
    const float em2 = __ldg(&enc_mean[2]), em3 = __ldg(&enc_mean[3]);
    const float rs0 = 1.0f / __ldg(&enc_std[0]), rs1 = 1.0f / __ldg(&enc_std[1]);
    const float rs2 = 1.0f / __ldg(&enc_std[2]), rs3 = 1.0f / __ldg(&enc_std[3]);

    // batch independent global loads (MLP across the 2 anchors)
    const int IP = K3A / K3T;   // 2
    int a[IP]; bool v[IP];
    unsigned long long ab[IP];
    float4 anc[IP];
    #pragma unroll
    for (int h = 0; h < IP; h++) {
        a[h] = abase + h * K3T + tid;
        v[h] = (a[h] < A);
        if (v[h]) {
            ab[h]  = g_abest[(size_t)b * A + a[h]];
            anc[h] = __ldg(&anchors[a[h]]);
        }
    }

    #pragma unroll
    for (int h = 0; h < IP; h++) {
        if (!v[h]) continue;
        const size_t base = (size_t)b * A + a[h];

        float miou = __uint_as_float((unsigned)(ab[h] >> 32));
        int   idx  = (int)(unsigned)ab[h];
        int w = swin[h * K3T + tid];
        if (w >= 0) { idx = w; miou = smiou[w]; }

        float den = fmaxf(smiou[idx], thr);
        if (miou < thr * 0.5f) miou = 0.f;
        float score = miou / den;

        int lab = slab[idx];
        if (lab <= 0) { score = 0.f; lab = 0; }

        for (int c = 0; c < C; c++)
            out_conf[base * C + c] = (lab == c + 1) ? score : 0.f;

        float4 m = sbox[idx];
        float mcx = (m.x + m.z) * 0.5f, mcy = (m.y + m.w) * 0.5f;
        float mw  = m.z - m.x,          mh  = m.w - m.y;
        float d0 = (mcx - anc[h].x) / anc[h].z;
        float d1 = (mcy - anc[h].y) / anc[h].w;
        float d2 = __logf(mw / anc[h].z);
        float d3 = __logf(mh / anc[h].w);
        float4 dv;
        dv.x = (d0 - em0) * rs0;
        dv.y = (d1 - em1) * rs1;
        dv.z = (d2 - em2) * rs2;
        dv.w = (d3 - em3) * rs3;
        out_delta[base] = dv;
    }
}

extern "C" void kernel_launch(void* const* d_in, const int* in_sizes, int n_in,
                              void* d_out, int out_size)
{
    const float* anchors = (const float*)d_in[0];
    const int*   labels  = (const int*)d_in[1];
    const float* bboxes  = (const float*)d_in[2];
    const float* emean   = (const float*)d_in[3];
    const float* estd    = (const float*)d_in[4];
    const float* thr     = (const float*)d_in[5];

    const int A  = in_sizes[0] / 4;          // anchors [A,4]
    const int BN = in_sizes[1];              // labels [B,N]
    int B = out_size / (5 * A);
    if (B <= 0) B = 1;
    const int N = BN / B;
    const int C = (int)((long)out_size / ((long)B * A)) - 4;

    const float4* anc4 = (const float4*)anchors;
    const float4* box4 = (const float4*)bboxes;

    const int numChunks = (A + CHUNK - 1) / CHUNK;
    dim3 grid1(numChunks, B);
    k_phase1<<<grid1, TPB>>>(anc4, box4, A, N, numChunks);

    k_phase2<<<B * N, 64>>>(A, N, numChunks);

    float*  out_conf  = (float*)d_out;
    float4* out_delta = (float4*)((float*)d_out + (size_t)B * A * C);
    dim3 g3((A + K3A - 1) / K3A, B);
    k_phase3<<<g3, K3T>>>(anc4, box4, labels, emean, estd, thr,
                          out_conf, out_delta, A, N, C);
}

// round 16
// speedup vs baseline: 1.0350x; 1.0350x over previous
#include <cuda_runtime.h>

#define TPB 128
#define APT 4                 // anchors per thread (k_phase1)
#define CHUNK (TPB * APT)     // anchors per block = 512
#define NW   (TPB / 32)       // warps per block
#define MAXN 128              // max gt boxes per image supported
#define MAXB 16               // max batch
#define K3T 256               // k_phase3 threads
#define K3A 512               // anchors per k_phase3 block

// Scratch (device globals; no allocation allowed)
__device__ unsigned long long g_partial[1 << 19];  // per-(b,n) per-chunk best keys
__device__ unsigned long long g_abest[1 << 20];    // per-(b,a) packed (iou, box idx)
__device__ float2             g_nbest[MAXB * MAXN];// per-(b,n): (miou, argmax anchor)

// K1: for each (batch, 512-anchor chunk): compute all IoUs vs N boxes once.
//  - per-anchor best (axis=1 argmax, strict > = first occurrence) -> g_abest
//  - per-box block-best (axis=0 argmax candidate, tie -> lowest anchor) -> g_partial
__global__ void __launch_bounds__(TPB)
k_phase1(const float4* __restrict__ anchors, const float4* __restrict__ bboxes,
         int A, int N, int numChunks)
{
    __shared__ float4 sbox[MAXN];
    __shared__ float  sarea[MAXN];
    __shared__ unsigned long long swb[MAXN * NW];

    const int b = blockIdx.y, chunk = blockIdx.x, tid = threadIdx.x;
    const int lane = tid & 31, wid = tid >> 5;

    for (int n = tid; n < N; n += TPB) {
        float4 bb = bboxes[b * N + n];
        sbox[n] = bb;
        sarea[n] = (bb.z - bb.x) * (bb.w - bb.y);
    }
    __syncthreads();

    // Load APT anchors (stride TPB so within-warp anchor order == lane order)
    float ax1[APT], ay1[APT], ax2[APT], ay2[APT], areaA[APT];
    unsigned aidx[APT];
    bool avalid[APT];
    #pragma unroll
    for (int k = 0; k < APT; k++) {
        int a = chunk * CHUNK + k * TPB + tid;
        aidx[k] = (unsigned)a;
        avalid[k] = (a < A);
        if (avalid[k]) {
            float4 c = anchors[a];
            ax1[k] = c.x - c.z * 0.5f;  ay1[k] = c.y - c.w * 0.5f;
            ax2[k] = c.x + c.z * 0.5f;  ay2[k] = c.y + c.w * 0.5f;
            areaA[k] = (ax2[k] - ax1[k]) * (ay2[k] - ay1[k]);  // reference order
        } else {
            // dummy: zero extent -> IoU exactly 0 vs any valid box; index larger
            // than every real anchor so it never wins a tie-break.
            ax1[k] = 0.f; ay1[k] = 0.f; ax2[k] = 0.f; ay2[k] = 0.f;
            areaA[k] = 0.f;
        }
    }

    float bestI[APT];
    int   bestN[APT];
    #pragma unroll
    for (int k = 0; k < APT; k++) { bestI[k] = 0.0f; bestN[k] = 0; }

    #pragma unroll 4
    for (int n = 0; n < N; n++) {
        float4 bb = sbox[n];
        float sa = sarea[n];

        float iou[APT];
        #pragma unroll
        for (int k = 0; k < APT; k++) {
            float ltx = fmaxf(ax1[k], bb.x), lty = fmaxf(ay1[k], bb.y);
            float rbx = fminf(ax2[k], bb.z), rby = fminf(ay2[k], bb.w);
            float w = fmaxf(rbx - ltx, 0.f), h = fmaxf(rby - lty, 0.f);
            float inter = w * h;
            iou[k] = __fdividef(inter, areaA[k] + sa - inter);
        }

        // per-anchor running argmax (strict > = first occurrence)
        #pragma unroll
        for (int k = 0; k < APT; k++)
            if (iou[k] > bestI[k]) { bestI[k] = iou[k]; bestN[k] = n; }

        // merge the APT anchors (strict > keeps earlier = lower anchor index)
        float    mi = iou[0];
        unsigned wa = aidx[0];
        #pragma unroll
        for (int k = 1; k < APT; k++)
            if (iou[k] > mi) { mi = iou[k]; wa = aidx[k]; }

        // warp argmax over anchors for this box: max IoU (uint-monotone, IoU>=0),
        // tie -> min anchor index.
        unsigned u = __float_as_uint(mi);
        unsigned m = __reduce_max_sync(0xffffffffu, u);
        unsigned cand = (u == m) ? wa : 0xFFFFFFFFu;
        unsigned amin = __reduce_min_sync(0xffffffffu, cand);
        if (lane == 0)
            swb[n * NW + wid] =
                ((unsigned long long)m << 32) | (0xFFFFFFFFu - amin);
    }

    #pragma unroll
    for (int k = 0; k < APT; k++)
        if (avalid[k])
            g_abest[(size_t)b * A + aidx[k]] =
                ((unsigned long long)__float_as_uint(bestI[k]) << 32) |
                (unsigned)bestN[k];

    __syncthreads();
    for (int n = tid; n < N; n += TPB) {
        unsigned long long best = swb[n * NW];
        #pragma unroll
        for (int w8 = 1; w8 < NW; w8++)
            if (swb[n * NW + w8] > best) best = swb[n * NW + w8];
        g_partial[((size_t)(b * N + n)) * numChunks + chunk] = best;
    }
}

// K2: reduce chunk partials per (b,n) -> (max_iou_of_bbox, anchor argmax).
__global__ void __launch_bounds__(64)
k_phase2(int A, int N, int numChunks)
{
    const int bn = blockIdx.x, tid = threadIdx.x;
    const unsigned long long* p = g_partial + (size_t)bn * numChunks;

    unsigned long long key = 0;
    for (int c = tid; c < numChunks; c += 64) {
        unsigned long long v = p[c];
        if (v > key) key = v;
    }
    __shared__ unsigned long long sred[2];
    #pragma unroll
    for (int off = 16; off; off >>= 1) {
        unsigned long long o = __shfl_down_sync(0xffffffffu, key, off);
        if (o > key) key = o;
    }
    if ((tid & 31) == 0) sred[tid >> 5] = key;
    __syncthreads();
    if (tid == 0) {
        if (sred[1] > key) key = sred[1];
        float miou = __uint_as_float((unsigned)(key >> 32));
        int   idx  = (int)(0xFFFFFFFFu - (unsigned)key);
        g_nbest[bn] = make_float2(miou, __int_as_float(idx));
    }
}

// K3: epilogue per 512-anchor block. Winner (segment_max over targets) is
// rebuilt LOCALLY in smem from the 100 per-box argmax anchors (identical to a
// global segment_max scatter, but read back via LDS instead of dependent LDG).
__global__ void __launch_bounds__(K3T)
k_phase3(const float4* __restrict__ anchors, const float4* __restrict__ bboxes,
         const int* __restrict__ labels,
         const float* __restrict__ enc_mean, const float* __restrict__ enc_std,
         const float* __restrict__ thr_ptr,
         float* __restrict__ out_conf, float4* __restrict__ out_delta,
         int A, int N, int C)
{
    __shared__ float4 sbox[MAXN];
    __shared__ int    slab[MAXN];
    __shared__ float  smiou[MAXN];
    __shared__ int    saw[MAXN];
    __shared__ int    swin[K3A];

    const int b = blockIdx.y, tid = threadIdx.x;
    const int abase = blockIdx.x * K3A;

    for (int n = tid; n < N; n += K3T) {
        sbox[n]  = bboxes[b * N + n];
        slab[n]  = labels[b * N + n];
        float2 nb = g_nbest[b * N + n];
        smiou[n] = nb.x;
        saw[n]   = __float_as_int(nb.y);
    }
    #pragma unroll
    for (int h = 0; h < K3A / K3T; h++) swin[h * K3T + tid] = -1;
    __syncthreads();

    // segment_max scatter restricted to this block's anchor range
    for (int n = tid; n < N; n += K3T) {
        int aw = saw[n] - abase;
        if ((unsigned)aw < (unsigned)K3A) atomicMax(&swin[aw], n);
    }
    __syncthreads();

    const float thr = __ldg(thr_ptr);
    const float em0 = __ldg(&enc_mean[0]), em1 = __ldg(&enc_mean[1]);
    const float em2 = __ldg(&enc_mean[2]), em3 = __ldg(&enc_mean[3]);
    const float rs0 = 1.0f / __ldg(&enc_std[0]), rs1 = 1.0f / __ldg(&enc_std[1]);
    const float rs2 = 1.0f / __ldg(&enc_std[2]), rs3 = 1.0f / __ldg(&enc_std[3]);

    // batch independent global loads (MLP across the 2 anchors)
    const int IP = K3A / K3T;   // 2
    int a[IP]; bool v[IP];
    unsigned long long ab[IP];
    float4 anc[IP];
    #pragma unroll
    for (int h = 0; h < IP; h++) {
        a[h] = abase + h * K3T + tid;
        v[h] = (a[h] < A);
        if (v[h]) {
            ab[h]  = g_abest[(size_t)b * A + a[h]];
            anc[h] = __ldg(&anchors[a[h]]);
        }
    }

    #pragma unroll
    for (int h = 0; h < IP; h++) {
        if (!v[h]) continue;
        const size_t base = (size_t)b * A + a[h];

        float miou = __uint_as_float((unsigned)(ab[h] >> 32));
        int   idx  = (int)(unsigned)ab[h];
        int w = swin[h * K3T + tid];
        if (w >= 0) { idx = w; miou = smiou[w]; }

        float den = fmaxf(smiou[idx], thr);
        if (miou < thr * 0.5f) miou = 0.f;
        float score = miou / den;

        int lab = slab[idx];
        if (lab <= 0) { score = 0.f; lab = 0; }

        for (int c = 0; c < C; c++)
            out_conf[base * C + c] = (lab == c + 1) ? score : 0.f;

        float4 m = sbox[idx];
        float mcx = (m.x + m.z) * 0.5f, mcy = (m.y + m.w) * 0.5f;
        float mw  = m.z - m.x,          mh  = m.w - m.y;
        float d0 = (mcx - anc[h].x) / anc[h].z;
        float d1 = (mcy - anc[h].y) / anc[h].w;
        float d2 = __logf(mw / anc[h].z);
        float d3 = __logf(mh / anc[h].w);
        float4 dv;
        dv.x = (d0 - em0) * rs0;
        dv.y = (d1 - em1) * rs1;
        dv.z = (d2 - em2) * rs2;
        dv.w = (d3 - em3) * rs3;
        out_delta[base] = dv;
    }
}

extern "C" void kernel_launch(void* const* d_in, const int* in_sizes, int n_in,
                              void* d_out, int out_size)
{
    const float* anchors = (const float*)d_in[0];
    const int*   labels  = (const int*)d_in[1];
    const float* bboxes  = (const float*)d_in[2];
    const float* emean   = (const float*)d_in[3];
    const float* estd    = (const float*)d_in[4];
    const float* thr     = (const float*)d_in[5];

    const int A  = in_sizes[0] / 4;          // anchors [A,4]
    const int BN = in_sizes[1];              // labels [B,N]
    int B = out_size / (5 * A);
    if (B <= 0) B = 1;
    const int N = BN / B;
    const int C = (int)((long)out_size / ((long)B * A)) - 4;

    const float4* anc4 = (const float4*)anchors;
    const float4* box4 = (const float4*)bboxes;

    const int numChunks = (A + CHUNK - 1) / CHUNK;
    dim3 grid1(numChunks, B);
    k_phase1<<<grid1, TPB>>>(anc4, box4, A, N, numChunks);

    k_phase2<<<B * N, 64>>>(A, N, numChunks);

    float*  out_conf  = (float*)d_out;
    float4* out_delta = (float4*)((float*)d_out + (size_t)B * A * C);
    dim3 g3((A + K3A - 1) / K3A, B);
    k_phase3<<<g3, K3T>>>(anc4, box4, labels, emean, estd, thr,
                          out_conf, out_delta, A, N, C);
}

// round 17
// speedup vs baseline: 1.1455x; 1.1068x over previous
#include <cuda_runtime.h>

#define TPB 128
#define APT 4                 // anchors per thread (k_phase1)
#define CHUNK (TPB * APT)     // anchors per block = 512
#define NW   (TPB / 32)       // warps per block
#define MAXN 128              // max gt boxes per image supported
#define MAXB 16               // max batch
#define K3T 256               // k_phase3 threads
#define K3A 512               // anchors per k_phase3 block
#define SCL 0.0009765625f     // 2^-10: exact power-of-two coordinate scale

// Scratch (device globals; no allocation allowed)
__device__ unsigned long long g_partial[1 << 19];  // per-(b,n) per-chunk best keys
__device__ unsigned long long g_abest[1 << 20];    // per-(b,a) packed (iou, box idx)
__device__ float2             g_nbest[MAXB * MAXN];// per-(b,n): (miou, argmax anchor)

// K1: for each (batch, 512-anchor chunk): compute all IoUs vs N boxes once.
//  - per-anchor best (axis=1 argmax, strict > = first occurrence) -> g_abest
//  - per-box block-best (axis=0 argmax candidate, tie -> lowest anchor) -> g_partial
//  All coordinates pre-scaled by 2^-10 (exact): min/max/sub scale exactly,
//  areas/products scale by 2^-20 exactly, and the IoU quotient is therefore
//  BIT-IDENTICAL to the unscaled computation. After scaling, overlap extents
//  are < 1, so the zero-clamp becomes __saturatef -> folds into FADD.SAT on
//  the fma pipe, removing 2 FMNMX/pair from the saturated alu pipe.
__global__ void __launch_bounds__(TPB)
k_phase1(const float4* __restrict__ anchors, const float4* __restrict__ bboxes,
         int A, int N, int numChunks)
{
    __shared__ float4 sbox[MAXN];
    __shared__ float  sarea[MAXN];
    __shared__ unsigned long long swb[MAXN * NW];

    const int b = blockIdx.y, chunk = blockIdx.x, tid = threadIdx.x;
    const int lane = tid & 31, wid = tid >> 5;

    for (int n = tid; n < N; n += TPB) {
        float4 bb = bboxes[b * N + n];
        bb.x *= SCL; bb.y *= SCL; bb.z *= SCL; bb.w *= SCL;   // exact
        sbox[n] = bb;
        sarea[n] = (bb.z - bb.x) * (bb.w - bb.y);
    }
    __syncthreads();

    // Load APT anchors (stride TPB so within-warp anchor order == lane order)
    float ax1[APT], ay1[APT], ax2[APT], ay2[APT], areaA[APT];
    unsigned aidx[APT];
    bool avalid[APT];
    #pragma unroll
    for (int k = 0; k < APT; k++) {
        int a = chunk * CHUNK + k * TPB + tid;
        aidx[k] = (unsigned)a;
        avalid[k] = (a < A);
        if (avalid[k]) {
            float4 c = anchors[a];
            // scale AFTER the cbox->bbox transform so the arithmetic lattice
            // matches the reference exactly (then exact 2^-10 scaling).
            ax1[k] = (c.x - c.z * 0.5f) * SCL;  ay1[k] = (c.y - c.w * 0.5f) * SCL;
            ax2[k] = (c.x + c.z * 0.5f) * SCL;  ay2[k] = (c.y + c.w * 0.5f) * SCL;
            areaA[k] = (ax2[k] - ax1[k]) * (ay2[k] - ay1[k]);
        } else {
            // dummy: zero extent -> IoU exactly 0 vs any valid box; index larger
            // than every real anchor so it never wins a tie-break.
            ax1[k] = 0.f; ay1[k] = 0.f; ax2[k] = 0.f; ay2[k] = 0.f;
            areaA[k] = 0.f;
        }
    }

    float bestI[APT];
    int   bestN[APT];
    #pragma unroll
    for (int k = 0; k < APT; k++) { bestI[k] = 0.0f; bestN[k] = 0; }

    #pragma unroll 2
    for (int n = 0; n < N; n++) {
        float4 bb = sbox[n];
        float sa = sarea[n];

        float iou[APT];
        #pragma unroll
        for (int k = 0; k < APT; k++) {
            float ltx = fmaxf(ax1[k], bb.x), lty = fmaxf(ay1[k], bb.y);
            float rbx = fminf(ax2[k], bb.z), rby = fminf(ay2[k], bb.w);
            // scaled extents < 1 -> saturate == clamp-at-0 (upper never hits);
            // folds into FADD.SAT on the fma pipe.
            float w = __saturatef(rbx - ltx), h = __saturatef(rby - lty);
            float inter = w * h;
            iou[k] = __fdividef(inter, areaA[k] + sa - inter);
        }

        // per-anchor running argmax (strict > = first occurrence)
        #pragma unroll
        for (int k = 0; k < APT; k++)
            if (iou[k] > bestI[k]) { bestI[k] = iou[k]; bestN[k] = n; }

        // merge the APT anchors (strict > keeps earlier = lower anchor index)
        float    mi = iou[0];
        unsigned wa = aidx[0];
        #pragma unroll
        for (int k = 1; k < APT; k++)
            if (iou[k] > mi) { mi = iou[k]; wa = aidx[k]; }

        // warp argmax over anchors for this box: max IoU (uint-monotone, IoU>=0),
        // tie -> min anchor index.
        unsigned u = __float_as_uint(mi);
        unsigned m = __reduce_max_sync(0xffffffffu, u);
        unsigned cand = (u == m) ? wa : 0xFFFFFFFFu;
        unsigned amin = __reduce_min_sync(0xffffffffu, cand);
        if (lane == 0)
            swb[n * NW + wid] =
                ((unsigned long long)m << 32) | (0xFFFFFFFFu - amin);
    }

    #pragma unroll
    for (int k = 0; k < APT; k++)
        if (avalid[k])
            g_abest[(size_t)b * A + aidx[k]] =
                ((unsigned long long)__float_as_uint(bestI[k]) << 32) |
                (unsigned)bestN[k];

    __syncthreads();
    for (int n = tid; n < N; n += TPB) {
        unsigned long long best = swb[n * NW];
        #pragma unroll
        for (int w8 = 1; w8 < NW; w8++)
            if (swb[n * NW + w8] > best) best = swb[n * NW + w8];
        g_partial[((size_t)(b * N + n)) * numChunks + chunk] = best;
    }
}

// K2: reduce chunk partials per (b,n) -> (max_iou_of_bbox, anchor argmax).
__global__ void __launch_bounds__(64)
k_phase2(int A, int N, int numChunks)
{
    const int bn = blockIdx.x, tid = threadIdx.x;
    const unsigned long long* p = g_partial + (size_t)bn * numChunks;

    unsigned long long key = 0;
    for (int c = tid; c < numChunks; c += 64) {
        unsigned long long v = p[c];
        if (v > key) key = v;
    }
    __shared__ unsigned long long sred[2];
    #pragma unroll
    for (int off = 16; off; off >>= 1) {
        unsigned long long o = __shfl_down_sync(0xffffffffu, key, off);
        if (o > key) key = o;
    }
    if ((tid & 31) == 0) sred[tid >> 5] = key;
    __syncthreads();
    if (tid == 0) {
        if (sred[1] > key) key = sred[1];
        float miou = __uint_as_float((unsigned)(key >> 32));
        int   idx  = (int)(0xFFFFFFFFu - (unsigned)key);
        g_nbest[bn] = make_float2(miou, __int_as_float(idx));
    }
}

// K3: epilogue per 512-anchor block. Winner (segment_max over targets) is
// rebuilt LOCALLY in smem from the 100 per-box argmax anchors.
__global__ void __launch_bounds__(K3T)
k_phase3(const float4* __restrict__ anchors, const float4* __restrict__ bboxes,
         const int* __restrict__ labels,
         const float* __restrict__ enc_mean, const float* __restrict__ enc_std,
         const float* __restrict__ thr_ptr,
         float* __restrict__ out_conf, float4* __restrict__ out_delta,
         int A, int N, int C)
{
    __shared__ float4 sbox[MAXN];
    __shared__ int    slab[MAXN];
    __shared__ float  smiou[MAXN];
    __shared__ int    saw[MAXN];
    __shared__ int    swin[K3A];

    const int b = blockIdx.y, tid = threadIdx.x;
    const int abase = blockIdx.x * K3A;

    for (int n = tid; n < N; n += K3T) {
        sbox[n]  = bboxes[b * N + n];
        slab[n]  = labels[b * N + n];
        float2 nb = g_nbest[b * N + n];
        smiou[n] = nb.x;
        saw[n]   = __float_as_int(nb.y);
    }
    #pragma unroll
    for (int h = 0; h < K3A / K3T; h++) swin[h * K3T + tid] = -1;
    __syncthreads();

    // segment_max scatter restricted to this block's anchor range
    for (int n = tid; n < N; n += K3T) {
        int aw = saw[n] - abase;
        if ((unsigned)aw < (unsigned)K3A) atomicMax(&swin[aw], n);
    }
    __syncthreads();

    const float thr = __ldg(thr_ptr);
    const float em0 = __ldg(&enc_mean[0]), em1 = __ldg(&enc_mean[1]);
    const float em2 = __ldg(&enc_mean[2]), em3 = __ldg(&enc_mean[3]);
    const float rs0 = 1.0f / __ldg(&enc_std[0]), rs1 = 1.0f / __ldg(&enc_std[1]);
    const float rs2 = 1.0f / __ldg(&enc_std[2]), rs3 = 1.0f / __ldg(&enc_std[3]);

    // batch independent global loads (MLP across the 2 anchors)
    const int IP = K3A / K3T;   // 2
    int a[IP]; bool v[IP];
    unsigned long long ab[IP];
    float4 anc[IP];
    #pragma unroll
    for (int h = 0; h < IP; h++) {
        a[h] = abase + h * K3T + tid;
        v[h] = (a[h] < A);
        if (v[h]) {
            ab[h]  = g_abest[(size_t)b * A + a[h]];
            anc[h] = __ldg(&anchors[a[h]]);
        }
    }

    #pragma unroll
    for (int h = 0; h < IP; h++) {
        if (!v[h]) continue;
        const size_t base = (size_t)b * A + a[h];

        float miou = __uint_as_float((unsigned)(ab[h] >> 32));
        int   idx  = (int)(unsigned)ab[h];
        int w = swin[h * K3T + tid];
        if (w >= 0) { idx = w; miou = smiou[w]; }

        float den = fmaxf(smiou[idx], thr);
        if (miou < thr * 0.5f) miou = 0.f;
        float score = miou / den;

        int lab = slab[idx];
        if (lab <= 0) { score = 0.f; lab = 0; }

        for (int c = 0; c < C; c++)
            out_conf[base * C + c] = (lab == c + 1) ? score : 0.f;

        float4 m = sbox[idx];
        float mcx = (m.x + m.z) * 0.5f, mcy = (m.y + m.w) * 0.5f;
        float mw  = m.z - m.x,          mh  = m.w - m.y;
        float d0 = (mcx - anc[h].x) / anc[h].z;
        float d1 = (mcy - anc[h].y) / anc[h].w;
        float d2 = __logf(mw / anc[h].z);
        float d3 = __logf(mh / anc[h].w);
        float4 dv;
        dv.x = (d0 - em0) * rs0;
        dv.y = (d1 - em1) * rs1;
        dv.z = (d2 - em2) * rs2;
        dv.w = (d3 - em3) * rs3;
        out_delta[base] = dv;
    }
}

extern "C" void kernel_launch(void* const* d_in, const int* in_sizes, int n_in,
                              void* d_out, int out_size)
{
    const float* anchors = (const float*)d_in[0];
    const int*   labels  = (const int*)d_in[1];
    const float* bboxes  = (const float*)d_in[2];
    const float* emean   = (const float*)d_in[3];
    const float* estd    = (const float*)d_in[4];
    const float* thr     = (const float*)d_in[5];

    const int A  = in_sizes[0] / 4;          // anchors [A,4]
    const int BN = in_sizes[1];              // labels [B,N]
    int B = out_size / (5 * A);
    if (B <= 0) B = 1;
    const int N = BN / B;
    const int C = (int)((long)out_size / ((long)B * A)) - 4;

    const float4* anc4 = (const float4*)anchors;
    const float4* box4 = (const float4*)bboxes;

    const int numChunks = (A + CHUNK - 1) / CHUNK;
    dim3 grid1(numChunks, B);
    k_phase1<<<grid1, TPB>>>(anc4, box4, A, N, numChunks);

    k_phase2<<<B * N, 64>>>(A, N, numChunks);

    float*  out_conf  = (float*)d_out;
    float4* out_delta = (float4*)((float*)d_out + (size_t)B * A * C);
    dim3 g3((A + K3A - 1) / K3A, B);
    k_phase3<<<g3, K3T>>>(anc4, box4, labels, emean, estd, thr,
                          out_conf, out_delta, A, N, C);
}